// round 5
// baseline (speedup 1.0000x reference)
#include <cuda_runtime.h>
#include <math.h>
#include <stdint.h>

#define NUM_CLASSES 10
#define BLOCK 256
#define GRID 592                       // 148 SMs * 4 — co-resident via launch_bounds
#define NTHREADS (GRID * BLOCK)
#define TILE_ROWS 512
#define TILE_F4 (TILE_ROWS * NUM_CLASSES / 4)   // 1280 float4 per tile
#define TILE_BYTES (TILE_F4 * 16)               // 20480

// log(x) = logf(x * 2^-21) + 21*ln2  (shift folded into final math)
#define LOG_SCALE (4.76837158203125e-7f)   // 2^-21
#define LOG_SHIFT 21.0

__device__ float  g_hist_partial[GRID * NUM_CLASSES];
__device__ double g_partial_log[GRID];
__device__ double g_partial_sq[GRID];
__device__ unsigned int g_hist_ready = 0;  // reset by last block each run
__device__ unsigned int g_done = 0;        // reset by last block each run

__device__ __forceinline__ void cp_async16(uint32_t s_addr, const void* g_ptr) {
    asm volatile("cp.async.cg.shared.global [%0], [%1], 16;" :: "r"(s_addr), "l"(g_ptr));
}
#define CP_COMMIT() asm volatile("cp.async.commit_group;")
#define CP_WAIT1()  asm volatile("cp.async.wait_group 1;")

__global__ void __launch_bounds__(BLOCK, 4)
cse_fused_kernel(const float* __restrict__ outp, const int* __restrict__ tgt,
                 int n_rows, float* __restrict__ out) {
    __shared__ __align__(16) float s_tile[2][TILE_ROWS * NUM_CLASSES]; // 40960 B
    __shared__ unsigned int s_hist[NUM_CLASSES];
    __shared__ float  s_cnt[NUM_CLASSES];
    __shared__ double s_rl[BLOCK / 32];
    __shared__ double s_rq[BLOCK / 32];
    __shared__ bool s_last;

    const int tid = threadIdx.x;
    const int bid = blockIdx.x;
    const int n_tiles = n_rows / TILE_ROWS;
    const float4* __restrict__ in4 = reinterpret_cast<const float4*>(outp);
    const uint32_t s_base = (uint32_t)__cvta_generic_to_shared(&s_tile[0][0]);

    // ---- issue prefetch of this block's FIRST tile before doing anything else:
    //      hides tile-0 DRAM latency under the histogram phase.
    if (bid < n_tiles) {
        size_t g = (size_t)bid * TILE_F4;
#pragma unroll
        for (int k = 0; k < 5; k++)
            cp_async16(s_base + (uint32_t)(tid + k * BLOCK) * 16u,
                       in4 + g + tid + k * BLOCK);
    }
    CP_COMMIT();

    // ================= Phase A: histogram of target (int32 in [0,10)) ======
    if (tid < NUM_CLASSES) { s_hist[tid] = 0u; s_cnt[tid] = 0.0f; }
    __syncthreads();
    {
        unsigned int c[NUM_CLASSES];
#pragma unroll
        for (int j = 0; j < NUM_CLASSES; j++) c[j] = 0u;

        const int4* t4 = reinterpret_cast<const int4*>(tgt);
        const int n4 = n_rows >> 2;
        unsigned long long acc = 0ull;
        int since = 0;
        for (int i = bid * BLOCK + tid; i < n4; i += NTHREADS) {
            int4 v = __ldcs(&t4[i]);
            acc += 1ull << (6 * v.x);
            acc += 1ull << (6 * v.y);
            acc += 1ull << (6 * v.z);
            acc += 1ull << (6 * v.w);
            if (++since == 10) {          // <=40 increments per 6-bit field
#pragma unroll
                for (int j = 0; j < NUM_CLASSES; j++)
                    c[j] += (unsigned int)((acc >> (6 * j)) & 63ull);
                acc = 0ull; since = 0;
            }
        }
        if (since) {
#pragma unroll
            for (int j = 0; j < NUM_CLASSES; j++)
                c[j] += (unsigned int)((acc >> (6 * j)) & 63ull);
        }
        if (bid == 0 && tid == 0) {       // tail rows (n % 4)
            for (int r = (n_rows >> 2) << 2; r < n_rows; r++) c[tgt[r]]++;
        }
#pragma unroll
        for (int j = 0; j < NUM_CLASSES; j++)
            if (c[j]) atomicAdd(&s_hist[j], c[j]);
    }
    __syncthreads();
    if (tid < NUM_CLASSES)
        g_hist_partial[bid * NUM_CLASSES + tid] = (float)s_hist[tid];
    __threadfence();
    if (tid == 0) {
        atomicAdd(&g_hist_ready, 1u);
        while (*(volatile unsigned int*)&g_hist_ready < (unsigned int)GRID)
            __nanosleep(64);
        __threadfence();
    }
    __syncthreads();

    // reduce partials -> class counts (exact small integers in float)
    for (int idx = tid; idx < GRID * NUM_CLASSES; idx += BLOCK)
        atomicAdd(&s_cnt[idx % NUM_CLASSES], g_hist_partial[idx]);
    __syncthreads();

    float c[NUM_CLASSES];
#pragma unroll
    for (int j = 0; j < NUM_CLASSES; j++) c[j] = s_cnt[j];

    // ================= Phase B: streaming pass, cp.async double buffer ======
    double acc_log = 0.0;
    double acc_sq  = 0.0;
    float  prod    = 1.0f;
    int    pcnt    = 0;
    int    buf     = 0;

    for (int t = bid; t < n_tiles; t += GRID) {
        const int tn = t + GRID;
        if (tn < n_tiles) {                       // prefetch next tile -> other buffer
            size_t g = (size_t)tn * TILE_F4;
            uint32_t b = s_base + (uint32_t)(buf ^ 1) * TILE_BYTES;
#pragma unroll
            for (int k = 0; k < 5; k++)
                cp_async16(b + (uint32_t)(tid + k * BLOCK) * 16u,
                           in4 + g + tid + k * BLOCK);
        }
        CP_COMMIT();
        CP_WAIT1();                               // current buffer's copies done
        __syncthreads();

        // this thread's 2 rows: 20 floats, 16B-aligned (80B), conflict-free LDS
        const float4* my = reinterpret_cast<const float4*>(&s_tile[buf][0]) + tid * 5;
        float4 a0 = my[0], a1 = my[1], a2 = my[2], a3 = my[3], a4 = my[4];
        float v[20] = {a0.x, a0.y, a0.z, a0.w, a1.x, a1.y, a1.z, a1.w,
                       a2.x, a2.y, a2.z, a2.w, a3.x, a3.y, a3.z, a3.w,
                       a4.x, a4.y, a4.z, a4.w};

        float dot0 = 0.f, dot1 = 0.f, sq = 0.f;
#pragma unroll
        for (int j = 0; j < NUM_CLASSES; j++) {
            dot0 = fmaf(v[j], c[j], dot0);
            dot1 = fmaf(v[NUM_CLASSES + j], c[j], dot1);
        }
#pragma unroll
        for (int k = 0; k < 20; k++) sq = fmaf(v[k], v[k], sq);
        acc_sq += (double)sq;

        prod *= dot0 * LOG_SCALE;
        if (++pcnt == 8) { acc_log += (double)logf(prod); prod = 1.0f; pcnt = 0; }
        prod *= dot1 * LOG_SCALE;
        if (++pcnt == 8) { acc_log += (double)logf(prod); prod = 1.0f; pcnt = 0; }

        __syncthreads();                          // buffer free for next prefetch
        buf ^= 1;
    }

    // tail rows (n_rows % TILE_ROWS) directly from gmem, block 0
    const int tail_start = n_tiles * TILE_ROWS;
    if (bid == 0) {
        for (int r = tail_start + tid; r < n_rows; r += BLOCK) {
            const float* row = outp + (size_t)r * NUM_CLASSES;
            float dot = 0.f, sq = 0.f;
#pragma unroll
            for (int j = 0; j < NUM_CLASSES; j++) {
                float x = row[j];
                dot = fmaf(x, c[j], dot);
                sq  = fmaf(x, x, sq);
            }
            acc_sq  += (double)sq;
            acc_log += (double)logf(dot * LOG_SCALE);
        }
    }

    if (pcnt) acc_log += (double)logf(prod);

    // ================= block reduction (deterministic order) ===============
#pragma unroll
    for (int off = 16; off; off >>= 1) {
        acc_log += __shfl_down_sync(0xffffffffu, acc_log, off);
        acc_sq  += __shfl_down_sync(0xffffffffu, acc_sq,  off);
    }
    const int wid = tid >> 5, lane = tid & 31;
    if (lane == 0) { s_rl[wid] = acc_log; s_rq[wid] = acc_sq; }
    __syncthreads();
    if (tid == 0) {
        double a = 0.0, b = 0.0;
#pragma unroll
        for (int w = 0; w < BLOCK / 32; w++) { a += s_rl[w]; b += s_rq[w]; }
        g_partial_log[bid] = a;
        g_partial_sq[bid]  = b;
        __threadfence();
        unsigned int tkt = atomicAdd(&g_done, 1u);
        s_last = (tkt == (unsigned int)(GRID - 1));
    }
    __syncthreads();

    // ================= last block: final scalar =============================
    if (s_last) {
        __threadfence();
        double a = 0.0, b = 0.0;
        for (int i = tid; i < GRID; i += BLOCK) {
            a += g_partial_log[i];
            b += g_partial_sq[i];
        }
#pragma unroll
        for (int off = 16; off; off >>= 1) {
            a += __shfl_down_sync(0xffffffffu, a, off);
            b += __shfl_down_sync(0xffffffffu, b, off);
        }
        if (lane == 0) { s_rl[wid] = a; s_rq[wid] = b; }
        __syncthreads();
        if (tid == 0) {
            double sa = 0.0, sb = 0.0;
#pragma unroll
            for (int w = 0; w < BLOCK / 32; w++) { sa += s_rl[w]; sb += s_rq[w]; }
            double N = (double)n_rows;
            double mean_log_nom = sa / N + LOG_SHIFT * M_LN2;
            double log_denom = 0.5 * log(sb) + 0.5 * log(N);   // log(||o||_F * sqrt(N))
            out[0] = (float)(log_denom - mean_log_nom);
            g_done = 0;         // reset for next graph replay
            g_hist_ready = 0;
        }
    }
}

extern "C" void kernel_launch(void* const* d_in, const int* in_sizes, int n_in,
                              void* d_out, int out_size) {
    // Resolve inputs by size: outputs has NUM_CLASSES x the elements of target.
    int io = 0, it = 1;
    if (n_in >= 2 && in_sizes[1] > in_sizes[0]) { io = 1; it = 0; }
    const float* outputs = (const float*)d_in[io];
    const int*   tgt     = (const int*)d_in[it];      // int32
    const int    n_rows  = in_sizes[it];              // N samples
    float* out           = (float*)d_out;

    cse_fused_kernel<<<GRID, BLOCK>>>(outputs, tgt, n_rows, out);
}

// round 6
// speedup vs baseline: 1.4836x; 1.4836x over previous
#include <cuda_runtime.h>
#include <math.h>
#include <stdint.h>

#define NUM_CLASSES 10
#define BLOCK 256
#define GRID 444                       // 148 SMs * 3 — co-resident (reg+smem cap = 3/SM)
#define NTHREADS (GRID * BLOCK)
#define TILE_ROWS 512
#define TILE_F4 (TILE_ROWS * NUM_CLASSES / 4)   // 1280 float4 per tile

// log(x) = logf(x * 2^-21) + 21*ln2  (shift folded into final math)
#define LOG_SCALE (4.76837158203125e-7f)   // 2^-21
#define LOG_SHIFT 21.0

__device__ float  g_hist_partial[GRID * NUM_CLASSES];
__device__ double g_partial_log[GRID];
__device__ double g_partial_sq[GRID];
__device__ unsigned int g_hist_ready = 0;  // reset by last block each run
__device__ unsigned int g_done = 0;        // reset by last block each run

__global__ void __launch_bounds__(BLOCK, 3)
cse_fused_kernel(const float* __restrict__ outp, const int* __restrict__ tgt,
                 int n_rows, float* __restrict__ out) {
    __shared__ __align__(16) float s_tile[2][TILE_ROWS * NUM_CLASSES]; // 40960 B
    __shared__ unsigned int s_hist[NUM_CLASSES];
    __shared__ float  s_cnt[NUM_CLASSES];
    __shared__ double s_rl[BLOCK / 32];
    __shared__ double s_rq[BLOCK / 32];
    __shared__ bool s_last;

    const int tid = threadIdx.x;
    const int bid = blockIdx.x;
    const int n_tiles = n_rows / TILE_ROWS;
    const float4* __restrict__ in4 = reinterpret_cast<const float4*>(outp);

    // ================= Phase A: histogram of target (int32 in [0,10)) ======
    if (tid < NUM_CLASSES) { s_hist[tid] = 0u; s_cnt[tid] = 0.0f; }
    __syncthreads();
    {
        unsigned int c[NUM_CLASSES];
#pragma unroll
        for (int j = 0; j < NUM_CLASSES; j++) c[j] = 0u;

        const int4* t4 = reinterpret_cast<const int4*>(tgt);
        const int n4 = n_rows >> 2;
        unsigned long long acc = 0ull;
        int since = 0;
        for (int i = bid * BLOCK + tid; i < n4; i += NTHREADS) {
            int4 v = __ldcs(&t4[i]);
            acc += 1ull << (6 * v.x);
            acc += 1ull << (6 * v.y);
            acc += 1ull << (6 * v.z);
            acc += 1ull << (6 * v.w);
            if (++since == 10) {          // <=40 increments per 6-bit field
#pragma unroll
                for (int j = 0; j < NUM_CLASSES; j++)
                    c[j] += (unsigned int)((acc >> (6 * j)) & 63ull);
                acc = 0ull; since = 0;
            }
        }
        if (since) {
#pragma unroll
            for (int j = 0; j < NUM_CLASSES; j++)
                c[j] += (unsigned int)((acc >> (6 * j)) & 63ull);
        }
        if (bid == 0 && tid == 0) {       // tail rows (n % 4)
            for (int r = (n_rows >> 2) << 2; r < n_rows; r++) c[tgt[r]]++;
        }
#pragma unroll
        for (int j = 0; j < NUM_CLASSES; j++)
            if (c[j]) atomicAdd(&s_hist[j], c[j]);
    }
    __syncthreads();
    if (tid < NUM_CLASSES)
        g_hist_partial[bid * NUM_CLASSES + tid] = (float)s_hist[tid];
    __threadfence();
    if (tid == 0) {
        atomicAdd(&g_hist_ready, 1u);
        while (*(volatile unsigned int*)&g_hist_ready < (unsigned int)GRID)
            __nanosleep(64);
        __threadfence();
    }
    __syncthreads();

    // reduce partials -> class counts (exact small integers in float)
    for (int idx = tid; idx < GRID * NUM_CLASSES; idx += BLOCK)
        atomicAdd(&s_cnt[idx % NUM_CLASSES], g_hist_partial[idx]);
    __syncthreads();

    float c[NUM_CLASSES];
#pragma unroll
    for (int j = 0; j < NUM_CLASSES; j++) c[j] = s_cnt[j];

    // ================= Phase B: coalesced smem staging, reg double-buffer ===
    // iter: issue LDGs for tile t+GRID (regs) -> sync -> compute tile t from
    // smem -> STS regs to other buffer. ONE sync per tile; loads overlap
    // compute + barrier.
    double acc_log = 0.0;
    double acc_sq  = 0.0;
    float  prod    = 1.0f;
    int    pcnt    = 0;
    int    buf     = 0;

    float4 r0, r1, r2, r3, r4;
    // prologue: stage first tile
    if (bid < n_tiles) {
        const float4* g = in4 + (size_t)bid * TILE_F4 + tid;
        r0 = __ldcs(g + 0 * BLOCK);
        r1 = __ldcs(g + 1 * BLOCK);
        r2 = __ldcs(g + 2 * BLOCK);
        r3 = __ldcs(g + 3 * BLOCK);
        r4 = __ldcs(g + 4 * BLOCK);
        float4* s = reinterpret_cast<float4*>(&s_tile[0][0]) + tid;
        s[0 * BLOCK] = r0; s[1 * BLOCK] = r1; s[2 * BLOCK] = r2;
        s[3 * BLOCK] = r3; s[4 * BLOCK] = r4;
    }

    for (int t = bid; t < n_tiles; t += GRID) {
        const int tn = t + GRID;
        const bool have_next = (tn < n_tiles);
        if (have_next) {                  // issue loads early — in flight across sync+compute
            const float4* g = in4 + (size_t)tn * TILE_F4 + tid;
            r0 = __ldcs(g + 0 * BLOCK);
            r1 = __ldcs(g + 1 * BLOCK);
            r2 = __ldcs(g + 2 * BLOCK);
            r3 = __ldcs(g + 3 * BLOCK);
            r4 = __ldcs(g + 4 * BLOCK);
        }
        __syncthreads();                  // prev iter's STS into s_tile[buf] visible

        // compute: this thread's 2 rows (20 floats, 80B, conflict-free LDS.128)
        const float4* my = reinterpret_cast<const float4*>(&s_tile[buf][0]) + tid * 5;
        float dot0 = 0.f, dot1 = 0.f, sq = 0.f;
        {
            float4 a = my[0];             // cols 0-3 of row0
            dot0 = fmaf(a.x, c[0], fmaf(a.y, c[1], fmaf(a.z, c[2], a.w * c[3])));
            sq = fmaf(a.x, a.x, fmaf(a.y, a.y, fmaf(a.z, a.z, a.w * a.w)));
            a = my[1];                    // cols 4-7 of row0
            dot0 = fmaf(a.x, c[4], fmaf(a.y, c[5], fmaf(a.z, c[6], fmaf(a.w, c[7], dot0))));
            sq = fmaf(a.x, a.x, fmaf(a.y, a.y, fmaf(a.z, a.z, fmaf(a.w, a.w, sq))));
            a = my[2];                    // cols 8,9 row0 ; cols 0,1 row1
            dot0 = fmaf(a.x, c[8], fmaf(a.y, c[9], dot0));
            dot1 = fmaf(a.z, c[0], a.w * c[1]);
            sq = fmaf(a.x, a.x, fmaf(a.y, a.y, fmaf(a.z, a.z, fmaf(a.w, a.w, sq))));
            a = my[3];                    // cols 2-5 row1
            dot1 = fmaf(a.x, c[2], fmaf(a.y, c[3], fmaf(a.z, c[4], fmaf(a.w, c[5], dot1))));
            sq = fmaf(a.x, a.x, fmaf(a.y, a.y, fmaf(a.z, a.z, fmaf(a.w, a.w, sq))));
            a = my[4];                    // cols 6-9 row1
            dot1 = fmaf(a.x, c[6], fmaf(a.y, c[7], fmaf(a.z, c[8], fmaf(a.w, c[9], dot1))));
            sq = fmaf(a.x, a.x, fmaf(a.y, a.y, fmaf(a.z, a.z, fmaf(a.w, a.w, sq))));
        }
        acc_sq += (double)sq;

        prod *= dot0 * LOG_SCALE;
        if (++pcnt == 8) { acc_log += (double)logf(prod); prod = 1.0f; pcnt = 0; }
        prod *= dot1 * LOG_SCALE;
        if (++pcnt == 8) { acc_log += (double)logf(prod); prod = 1.0f; pcnt = 0; }

        if (have_next) {                  // stage next tile into the other buffer
            float4* s = reinterpret_cast<float4*>(&s_tile[buf ^ 1][0]) + tid;
            s[0 * BLOCK] = r0; s[1 * BLOCK] = r1; s[2 * BLOCK] = r2;
            s[3 * BLOCK] = r3; s[4 * BLOCK] = r4;
        }
        buf ^= 1;
    }

    // tail rows (n_rows % TILE_ROWS) directly from gmem, block 0
    const int tail_start = n_tiles * TILE_ROWS;
    if (bid == 0) {
        for (int r = tail_start + tid; r < n_rows; r += BLOCK) {
            const float* row = outp + (size_t)r * NUM_CLASSES;
            float dot = 0.f, sq = 0.f;
#pragma unroll
            for (int j = 0; j < NUM_CLASSES; j++) {
                float x = row[j];
                dot = fmaf(x, c[j], dot);
                sq  = fmaf(x, x, sq);
            }
            acc_sq  += (double)sq;
            acc_log += (double)logf(dot * LOG_SCALE);
        }
    }

    if (pcnt) acc_log += (double)logf(prod);

    // ================= block reduction (deterministic order) ===============
#pragma unroll
    for (int off = 16; off; off >>= 1) {
        acc_log += __shfl_down_sync(0xffffffffu, acc_log, off);
        acc_sq  += __shfl_down_sync(0xffffffffu, acc_sq,  off);
    }
    const int wid = tid >> 5, lane = tid & 31;
    if (lane == 0) { s_rl[wid] = acc_log; s_rq[wid] = acc_sq; }
    __syncthreads();
    if (tid == 0) {
        double a = 0.0, b = 0.0;
#pragma unroll
        for (int w = 0; w < BLOCK / 32; w++) { a += s_rl[w]; b += s_rq[w]; }
        g_partial_log[bid] = a;
        g_partial_sq[bid]  = b;
        __threadfence();
        unsigned int tkt = atomicAdd(&g_done, 1u);
        s_last = (tkt == (unsigned int)(GRID - 1));
    }
    __syncthreads();

    // ================= last block: final scalar =============================
    if (s_last) {
        __threadfence();
        double a = 0.0, b = 0.0;
        for (int i = tid; i < GRID; i += BLOCK) {
            a += g_partial_log[i];
            b += g_partial_sq[i];
        }
#pragma unroll
        for (int off = 16; off; off >>= 1) {
            a += __shfl_down_sync(0xffffffffu, a, off);
            b += __shfl_down_sync(0xffffffffu, b, off);
        }
        if (lane == 0) { s_rl[wid] = a; s_rq[wid] = b; }
        __syncthreads();
        if (tid == 0) {
            double sa = 0.0, sb = 0.0;
#pragma unroll
            for (int w = 0; w < BLOCK / 32; w++) { sa += s_rl[w]; sb += s_rq[w]; }
            double N = (double)n_rows;
            double mean_log_nom = sa / N + LOG_SHIFT * M_LN2;
            double log_denom = 0.5 * log(sb) + 0.5 * log(N);   // log(||o||_F * sqrt(N))
            out[0] = (float)(log_denom - mean_log_nom);
            g_done = 0;         // reset for next graph replay
            g_hist_ready = 0;
        }
    }
}

extern "C" void kernel_launch(void* const* d_in, const int* in_sizes, int n_in,
                              void* d_out, int out_size) {
    // Resolve inputs by size: outputs has NUM_CLASSES x the elements of target.
    int io = 0, it = 1;
    if (n_in >= 2 && in_sizes[1] > in_sizes[0]) { io = 1; it = 0; }
    const float* outputs = (const float*)d_in[io];
    const int*   tgt     = (const int*)d_in[it];      // int32
    const int    n_rows  = in_sizes[it];              // N samples
    float* out           = (float*)d_out;

    cse_fused_kernel<<<GRID, BLOCK>>>(outputs, tgt, n_rows, out);
}